// round 9
// baseline (speedup 1.0000x reference)
#include <cuda_runtime.h>
#include <cuda_fp16.h>
#include <cstdint>
#include <math.h>

// Problem shape (fixed)
#define Bb  4
#define Kk  8192
#define Dd  1024
#define Mm  (Bb * Kk)          // 32768 GEMM rows
#define NCH 128                // scan chunks along K
#define LCH (Kk / NCH)         // 64 steps per chunk
#define NCHAIN 8               // Bb * 2 channel-halves
#define THR 256                // threads per scan block (2 ch each -> 512 ch)

// Scratch (allocation-free rule: __device__ globals)
__device__ __half g_lamh[(size_t)Mm * Dd];    // 64 MiB fp16 lam
__device__ __half g_Xh[(size_t)Mm * Dd];      // 64 MiB fp16 X
__device__ __half g_Wh[(size_t)Dd * Dd];      // 2 MiB fp16 W
__device__ float2 g_pubA[NCHAIN * NCH * THR]; // chunk aggregate A (2 ch / thread)
__device__ float2 g_pubS[NCHAIN * NCH * THR]; // chunk aggregate S
__device__ unsigned g_flag[NCHAIN * NCH];     // 1 = aggregate published
__device__ unsigned g_ctr;                    // dynamic block index

// ---------------------------------------------------------------------------
// f32 -> f16 conversion (X and W), vectorized
// ---------------------------------------------------------------------------
__global__ __launch_bounds__(256) void f2h_kernel(const float4* __restrict__ src,
                                                  uint2* __restrict__ dst, int n4)
{
    int i = blockIdx.x * blockDim.x + threadIdx.x;
    const int stride = gridDim.x * blockDim.x;
    for (; i < n4; i += stride) {
        float4 v = src[i];
        __half2 h0 = __floats2half2_rn(v.x, v.y);
        __half2 h1 = __floats2half2_rn(v.z, v.w);
        uint2 o;
        o.x = *reinterpret_cast<unsigned*>(&h0);
        o.y = *reinterpret_cast<unsigned*>(&h1);
        dst[i] = o;
    }
}

// ---------------------------------------------------------------------------
// FP16 tensor-core GEMM + sigmoid epilogue:  g_lamh = sigmoid(X @ W^T + b)
// (unchanged from R8: 256 thr, 128x256x32 tiles, 4-stage cp.async, m16n8k16)
// ---------------------------------------------------------------------------
#define BM 128
#define BN 256
#define BK 32
#define PITH 40
#define NSTG 4
#define A_STGH (BM * PITH)
#define B_STGH (BN * PITH)
#define SMEM_HALVES (NSTG * (A_STGH + B_STGH))
#define NKT (Dd / BK)

__device__ __forceinline__ void cp16s(uint32_t smem_dst, const void* gmem_src) {
    asm volatile("cp.async.cg.shared.global [%0], [%1], 16;\n"
                 :: "r"(smem_dst), "l"(gmem_src));
}
__device__ __forceinline__ void cp_commit() {
    asm volatile("cp.async.commit_group;\n");
}
template <int N>
__device__ __forceinline__ void cp_wait() {
    asm volatile("cp.async.wait_group %0;\n" :: "n"(N));
}
__device__ __forceinline__ void mma_f16(float* d, const unsigned* a, const unsigned* b) {
    asm volatile(
        "mma.sync.aligned.m16n8k16.row.col.f32.f16.f16.f32 "
        "{%0,%1,%2,%3}, {%4,%5,%6,%7}, {%8,%9}, {%0,%1,%2,%3};\n"
        : "+f"(d[0]), "+f"(d[1]), "+f"(d[2]), "+f"(d[3])
        : "r"(a[0]), "r"(a[1]), "r"(a[2]), "r"(a[3]), "r"(b[0]), "r"(b[1]));
}

extern __shared__ __half smemh[];

__global__ __launch_bounds__(256, 1) void gemm_sigmoid_f16(
    const float* __restrict__ bias)
{
    __half* As = smemh;
    __half* Bs = smemh + NSTG * A_STGH;

    const int tid  = threadIdx.x;
    const int lane = tid & 31;
    const int wid  = tid >> 5;
    const int wm0  = (wid & 1) * 64;
    const int wn0  = (wid >> 1) * 64;
    const int g    = lane >> 2;
    const int q    = lane & 3;
    const int m0b  = blockIdx.y * BM;
    const int n0b  = blockIdx.x * BN;

    const uint32_t sA = (uint32_t)__cvta_generic_to_shared(As);
    const uint32_t sB = (uint32_t)__cvta_generic_to_shared(Bs);

    float acc[4][8][4];
    #pragma unroll
    for (int mi = 0; mi < 4; mi++)
        #pragma unroll
        for (int ni = 0; ni < 8; ni++)
            #pragma unroll
            for (int r = 0; r < 4; r++)
                acc[mi][ni][r] = 0.0f;

    auto load_stage = [&](int kt) {
        const int slot = kt & (NSTG - 1);
        const int k0   = kt * BK;
        const uint32_t abase = sA + slot * A_STGH * 2;
        const uint32_t bbase = sB + slot * B_STGH * 2;
        #pragma unroll
        for (int i = 0; i < 6; i++) {
            int idx = tid + i * 256;
            if (idx < 512) {
                int r = idx >> 2, c = idx & 3;
                cp16s(abase + (r * PITH + c * 8) * 2,
                      &g_Xh[(size_t)(m0b + r) * Dd + k0 + c * 8]);
            } else {
                int j = idx - 512;
                int r = j >> 2, c = j & 3;
                cp16s(bbase + (r * PITH + c * 8) * 2,
                      &g_Wh[(size_t)(n0b + r) * Dd + k0 + c * 8]);
            }
        }
        cp_commit();
    };

    load_stage(0);
    load_stage(1);
    load_stage(2);

    for (int kt = 0; kt < NKT; kt++) {
        if (kt + 3 < NKT) load_stage(kt + 3);
        else cp_commit();                  // keep group accounting exact at tail
        cp_wait<3>();
        __syncthreads();

        const int slot = kt & (NSTG - 1);
        const __half* Asl = &As[slot * A_STGH];
        const __half* Bsl = &Bs[slot * B_STGH];

        #pragma unroll
        for (int kf = 0; kf < BK; kf += 16) {
            unsigned af[4][4], bf[8][2];
            #pragma unroll
            for (int mi = 0; mi < 4; mi++) {
                int base = (wm0 + mi * 16 + g) * PITH + kf + 2 * q;
                af[mi][0] = *(const unsigned*)&Asl[base];
                af[mi][1] = *(const unsigned*)&Asl[base + 8 * PITH];
                af[mi][2] = *(const unsigned*)&Asl[base + 8];
                af[mi][3] = *(const unsigned*)&Asl[base + 8 * PITH + 8];
            }
            #pragma unroll
            for (int ni = 0; ni < 8; ni++) {
                int base = (wn0 + ni * 8 + g) * PITH + kf + 2 * q;
                bf[ni][0] = *(const unsigned*)&Bsl[base];
                bf[ni][1] = *(const unsigned*)&Bsl[base + 8];
            }
            #pragma unroll
            for (int mi = 0; mi < 4; mi++)
                #pragma unroll
                for (int ni = 0; ni < 8; ni++)
                    mma_f16(acc[mi][ni], af[mi], bf[ni]);
        }
        __syncthreads();
    }

    #pragma unroll
    for (int ni = 0; ni < 8; ni++) {
        const int c0 = n0b + wn0 + ni * 8 + 2 * q;
        const float b0 = bias[c0];
        const float b1 = bias[c0 + 1];
        #pragma unroll
        for (int mi = 0; mi < 4; mi++) {
            const int r0 = m0b + wm0 + mi * 16 + g;
            float z0 = acc[mi][ni][0] + b0, z1 = acc[mi][ni][1] + b1;
            float z2 = acc[mi][ni][2] + b0, z3 = acc[mi][ni][3] + b1;
            __half2 h0 = __floats2half2_rn(1.0f / (1.0f + __expf(-z0)),
                                           1.0f / (1.0f + __expf(-z1)));
            __half2 h1 = __floats2half2_rn(1.0f / (1.0f + __expf(-z2)),
                                           1.0f / (1.0f + __expf(-z3)));
            *(__half2*)&g_lamh[(size_t)r0 * Dd + c0]       = h0;
            *(__half2*)&g_lamh[(size_t)(r0 + 8) * Dd + c0] = h1;
        }
    }
}

// ---------------------------------------------------------------------------
// Fused scan: one block per (chain, chunk) tile of 64 k-steps x 512 channels.
// Pass A: local (A,S); publish aggregate (release flag).
// Lookback: fold ALL predecessor aggregates, descending j (deterministic).
// Pass B: re-scan tile from incoming prefix (L1/L2-hot re-read), write out.
// Dynamic block index guarantees lower chunks are resident first (no deadlock).
// ---------------------------------------------------------------------------
__device__ __forceinline__ unsigned ld_acq(const unsigned* p) {
    unsigned v;
    asm volatile("ld.acquire.gpu.global.u32 %0, [%1];" : "=r"(v) : "l"(p));
    return v;
}
__device__ __forceinline__ void st_rel(unsigned* p, unsigned v) {
    asm volatile("st.release.gpu.global.u32 [%0], %1;" :: "l"(p), "r"(v));
}

__global__ __launch_bounds__(THR) void scan_fused(float* __restrict__ out)
{
    __shared__ unsigned s_idx;
    const int tid = threadIdx.x;
    if (tid == 0) s_idx = atomicAdd(&g_ctr, 1u);
    __syncthreads();
    const unsigned idx = s_idx;

    const int c     = idx >> 3;        // chunk 0..127 (low chunks first)
    const int chain = idx & 7;         // b*2 + dgroup
    const int b     = chain >> 1;
    const int d     = (chain & 1) * 512 + tid * 2;
    const size_t base = ((size_t)(b * Kk + c * LCH)) * Dd + d;

    // ---- pass A: chunk summary ----
    float A0 = 1.0f, A1 = 1.0f, S0 = 0.0f, S1 = 0.0f;
    #pragma unroll 8
    for (int k = 0; k < LCH; k++) {
        size_t i = base + (size_t)k * Dd;
        float2 lam = __half22float2(*(const __half2*)&g_lamh[i]);
        float2 xv  = __half22float2(*(const __half2*)&g_Xh[i]);
        S0 = fmaf(lam.x, S0 - xv.x, xv.x);
        S1 = fmaf(lam.y, S1 - xv.y, xv.y);
        A0 *= lam.x;
        A1 *= lam.y;
    }

    // ---- publish aggregate ----
    const int slot = (chain * NCH + c) * THR + tid;
    g_pubA[slot] = make_float2(A0, A1);
    g_pubS[slot] = make_float2(S0, S1);
    __syncthreads();
    __threadfence();
    if (tid == 0) st_rel(&g_flag[chain * NCH + c], 1u);

    // ---- full-depth lookback (deterministic): fold chunks c-1 .. 0 ----
    float a0 = 1.0f, a1 = 1.0f, p0 = 0.0f, p1 = 0.0f;
    int j = c - 1;
    while (j >= 0) {
        int lo = j - 7; if (lo < 0) lo = 0;
        // wait for all flags in [lo..j]
        for (;;) {
            unsigned allr = 1u;
            #pragma unroll
            for (int t = 0; t < 8; t++) {
                int jj = j - t;
                if (jj >= lo) allr &= ld_acq(&g_flag[chain * NCH + jj]);
            }
            if (allr) break;
        }
        #pragma unroll
        for (int t = 0; t < 8; t++) {
            int jj = j - t;
            if (jj >= lo) {
                int ps = (chain * NCH + jj) * THR + tid;
                float2 Aj = g_pubA[ps];
                float2 Sj = g_pubS[ps];
                p0 = fmaf(a0, Sj.x, p0); a0 *= Aj.x;
                p1 = fmaf(a1, Sj.y, p1); a1 *= Aj.y;
            }
        }
        j = lo - 1;
    }
    // incoming state (s_{-1} = 0): s_in = p

    // ---- pass B: re-scan from prefix, write output ----
    float s0 = p0, s1 = p1;
    #pragma unroll 8
    for (int k = 0; k < LCH; k++) {
        size_t i = base + (size_t)k * Dd;
        float2 lam = __half22float2(*(const __half2*)&g_lamh[i]);
        float2 xv  = __half22float2(*(const __half2*)&g_Xh[i]);
        s0 = fmaf(lam.x, s0 - xv.x, xv.x);
        s1 = fmaf(lam.y, s1 - xv.y, xv.y);
        *(float2*)&out[i] = make_float2(s0, s1);
    }
}

// ---------------------------------------------------------------------------
extern "C" void kernel_launch(void* const* d_in, const int* in_sizes, int n_in,
                              void* d_out, int out_size)
{
    const float* X    = (const float*)d_in[0];  // [B,K,D]
    const float* W    = (const float*)d_in[1];  // [D,D]
    const float* bias = (const float*)d_in[2];  // [D]
    float* out        = (float*)d_out;          // [B,K,D]

    // reset lookback state (graph replays!)
    void *flagp, *ctrp;
    cudaGetSymbolAddress(&flagp, g_flag);
    cudaGetSymbolAddress(&ctrp, g_ctr);
    cudaMemsetAsync(flagp, 0, NCHAIN * NCH * sizeof(unsigned));
    cudaMemsetAsync(ctrp, 0, sizeof(unsigned));

    __half* Xh; cudaGetSymbolAddress((void**)&Xh, g_Xh);
    __half* Wh; cudaGetSymbolAddress((void**)&Wh, g_Wh);
    f2h_kernel<<<1024, 256>>>((const float4*)X, (uint2*)Xh, (Mm * Dd) / 4);
    f2h_kernel<<<256, 256>>>((const float4*)W, (uint2*)Wh, (Dd * Dd) / 4);

    const int smem_bytes = SMEM_HALVES * (int)sizeof(__half);   // 120 KB
    cudaFuncSetAttribute(gemm_sigmoid_f16,
                         cudaFuncAttributeMaxDynamicSharedMemorySize, smem_bytes);

    dim3 gemm_grid(Dd / BN, Mm / BM);           // (4, 256)
    gemm_sigmoid_f16<<<gemm_grid, 256, smem_bytes>>>(bias);

    scan_fused<<<NCHAIN * NCH, THR>>>(out);     // 1024 blocks
}

// round 10
// speedup vs baseline: 1.1916x; 1.1916x over previous
#include <cuda_runtime.h>
#include <cuda_fp16.h>
#include <cstdint>
#include <math.h>

// Problem shape (fixed)
#define Bb  4
#define Kk  8192
#define Dd  1024
#define Mm  (Bb * Kk)          // 32768 GEMM rows
#define NCH 256                // scan chunks along K
#define LCH (Kk / NCH)         // 32 steps per chunk
#define CHN (Bb * Dd)          // 4096 independent channels

// Scratch (allocation-free rule: __device__ globals)
__device__ __half g_lamh[(size_t)Mm * Dd];    // 64 MiB fp16 lam
__device__ __half g_Xh[(size_t)Mm * Dd];      // 64 MiB fp16 X
__device__ __half g_Wh[(size_t)Dd * Dd];      // 2 MiB fp16 W
__device__ float  g_A[NCH * CHN];
__device__ float  g_S[NCH * CHN];
__device__ float  g_P[NCH * CHN];

// ---------------------------------------------------------------------------
// f32 -> f16 conversion (X and W), vectorized
// ---------------------------------------------------------------------------
__global__ __launch_bounds__(256) void f2h_kernel(const float4* __restrict__ src,
                                                  uint2* __restrict__ dst, int n4)
{
    int i = blockIdx.x * blockDim.x + threadIdx.x;
    const int stride = gridDim.x * blockDim.x;
    for (; i < n4; i += stride) {
        float4 v = src[i];
        __half2 h0 = __floats2half2_rn(v.x, v.y);
        __half2 h1 = __floats2half2_rn(v.z, v.w);
        uint2 o;
        o.x = *reinterpret_cast<unsigned*>(&h0);
        o.y = *reinterpret_cast<unsigned*>(&h1);
        dst[i] = o;
    }
}

// ---------------------------------------------------------------------------
// FP16 tensor-core GEMM + sigmoid epilogue:  g_lamh = sigmoid(X @ W^T + b)
// (unchanged from R8: 256 thr, 128x256x32 tiles, 4-stage cp.async, m16n8k16)
// ---------------------------------------------------------------------------
#define BM 128
#define BN 256
#define BK 32
#define PITH 40
#define NSTG 4
#define A_STGH (BM * PITH)
#define B_STGH (BN * PITH)
#define SMEM_HALVES (NSTG * (A_STGH + B_STGH))
#define NKT (Dd / BK)

__device__ __forceinline__ void cp16s(uint32_t smem_dst, const void* gmem_src) {
    asm volatile("cp.async.cg.shared.global [%0], [%1], 16;\n"
                 :: "r"(smem_dst), "l"(gmem_src));
}
__device__ __forceinline__ void cp_commit() {
    asm volatile("cp.async.commit_group;\n");
}
template <int N>
__device__ __forceinline__ void cp_wait() {
    asm volatile("cp.async.wait_group %0;\n" :: "n"(N));
}
__device__ __forceinline__ void mma_f16(float* d, const unsigned* a, const unsigned* b) {
    asm volatile(
        "mma.sync.aligned.m16n8k16.row.col.f32.f16.f16.f32 "
        "{%0,%1,%2,%3}, {%4,%5,%6,%7}, {%8,%9}, {%0,%1,%2,%3};\n"
        : "+f"(d[0]), "+f"(d[1]), "+f"(d[2]), "+f"(d[3])
        : "r"(a[0]), "r"(a[1]), "r"(a[2]), "r"(a[3]), "r"(b[0]), "r"(b[1]));
}

extern __shared__ __half smemh[];

__global__ __launch_bounds__(256, 1) void gemm_sigmoid_f16(
    const float* __restrict__ bias)
{
    __half* As = smemh;
    __half* Bs = smemh + NSTG * A_STGH;

    const int tid  = threadIdx.x;
    const int lane = tid & 31;
    const int wid  = tid >> 5;
    const int wm0  = (wid & 1) * 64;
    const int wn0  = (wid >> 1) * 64;
    const int g    = lane >> 2;
    const int q    = lane & 3;
    const int m0b  = blockIdx.y * BM;
    const int n0b  = blockIdx.x * BN;

    const uint32_t sA = (uint32_t)__cvta_generic_to_shared(As);
    const uint32_t sB = (uint32_t)__cvta_generic_to_shared(Bs);

    float acc[4][8][4];
    #pragma unroll
    for (int mi = 0; mi < 4; mi++)
        #pragma unroll
        for (int ni = 0; ni < 8; ni++)
            #pragma unroll
            for (int r = 0; r < 4; r++)
                acc[mi][ni][r] = 0.0f;

    auto load_stage = [&](int kt) {
        const int slot = kt & (NSTG - 1);
        const int k0   = kt * BK;
        const uint32_t abase = sA + slot * A_STGH * 2;
        const uint32_t bbase = sB + slot * B_STGH * 2;
        #pragma unroll
        for (int i = 0; i < 6; i++) {
            int idx = tid + i * 256;
            if (idx < 512) {
                int r = idx >> 2, c = idx & 3;
                cp16s(abase + (r * PITH + c * 8) * 2,
                      &g_Xh[(size_t)(m0b + r) * Dd + k0 + c * 8]);
            } else {
                int j = idx - 512;
                int r = j >> 2, c = j & 3;
                cp16s(bbase + (r * PITH + c * 8) * 2,
                      &g_Wh[(size_t)(n0b + r) * Dd + k0 + c * 8]);
            }
        }
        cp_commit();
    };

    load_stage(0);
    load_stage(1);
    load_stage(2);

    for (int kt = 0; kt < NKT; kt++) {
        if (kt + 3 < NKT) load_stage(kt + 3);
        else cp_commit();                  // keep group accounting exact at tail
        cp_wait<3>();
        __syncthreads();

        const int slot = kt & (NSTG - 1);
        const __half* Asl = &As[slot * A_STGH];
        const __half* Bsl = &Bs[slot * B_STGH];

        #pragma unroll
        for (int kf = 0; kf < BK; kf += 16) {
            unsigned af[4][4], bf[8][2];
            #pragma unroll
            for (int mi = 0; mi < 4; mi++) {
                int base = (wm0 + mi * 16 + g) * PITH + kf + 2 * q;
                af[mi][0] = *(const unsigned*)&Asl[base];
                af[mi][1] = *(const unsigned*)&Asl[base + 8 * PITH];
                af[mi][2] = *(const unsigned*)&Asl[base + 8];
                af[mi][3] = *(const unsigned*)&Asl[base + 8 * PITH + 8];
            }
            #pragma unroll
            for (int ni = 0; ni < 8; ni++) {
                int base = (wn0 + ni * 8 + g) * PITH + kf + 2 * q;
                bf[ni][0] = *(const unsigned*)&Bsl[base];
                bf[ni][1] = *(const unsigned*)&Bsl[base + 8];
            }
            #pragma unroll
            for (int mi = 0; mi < 4; mi++)
                #pragma unroll
                for (int ni = 0; ni < 8; ni++)
                    mma_f16(acc[mi][ni], af[mi], bf[ni]);
        }
        __syncthreads();
    }

    #pragma unroll
    for (int ni = 0; ni < 8; ni++) {
        const int c0 = n0b + wn0 + ni * 8 + 2 * q;
        const float b0 = bias[c0];
        const float b1 = bias[c0 + 1];
        #pragma unroll
        for (int mi = 0; mi < 4; mi++) {
            const int r0 = m0b + wm0 + mi * 16 + g;
            float z0 = acc[mi][ni][0] + b0, z1 = acc[mi][ni][1] + b1;
            float z2 = acc[mi][ni][2] + b0, z3 = acc[mi][ni][3] + b1;
            __half2 h0 = __floats2half2_rn(1.0f / (1.0f + __expf(-z0)),
                                           1.0f / (1.0f + __expf(-z1)));
            __half2 h1 = __floats2half2_rn(1.0f / (1.0f + __expf(-z2)),
                                           1.0f / (1.0f + __expf(-z3)));
            *(__half2*)&g_lamh[(size_t)r0 * Dd + c0]       = h0;
            *(__half2*)&g_lamh[(size_t)(r0 + 8) * Dd + c0] = h1;
        }
    }
}

// ---------------------------------------------------------------------------
// Scan phase 1: 4 channels/thread (uint2 = 2x half2), grid (Bb, NCH) = 1024.
// ---------------------------------------------------------------------------
__global__ __launch_bounds__(256) void scan_phase1()
{
    const int d = threadIdx.x * 4;       // 256 threads x 4 ch = 1024 = Dd
    const int b = blockIdx.x;
    const int c = blockIdx.y;
    size_t base = ((size_t)(b * Kk + c * LCH)) * Dd + d;

    float s[4] = {0.f, 0.f, 0.f, 0.f};
    float A[4] = {1.f, 1.f, 1.f, 1.f};
    #pragma unroll 8
    for (int k = 0; k < LCH; k++) {
        size_t idx = base + (size_t)k * Dd;
        uint2 lu = *(const uint2*)&g_lamh[idx];
        uint2 xu = *(const uint2*)&g_Xh[idx];
        float2 l0 = __half22float2(*(__half2*)&lu.x);
        float2 l1 = __half22float2(*(__half2*)&lu.y);
        float2 x0 = __half22float2(*(__half2*)&xu.x);
        float2 x1 = __half22float2(*(__half2*)&xu.y);
        s[0] = fmaf(l0.x, s[0] - x0.x, x0.x); A[0] *= l0.x;
        s[1] = fmaf(l0.y, s[1] - x0.y, x0.y); A[1] *= l0.y;
        s[2] = fmaf(l1.x, s[2] - x1.x, x1.x); A[2] *= l1.x;
        s[3] = fmaf(l1.y, s[3] - x1.y, x1.y); A[3] *= l1.y;
    }
    const int ch = b * Dd + d;
    *(float4*)&g_A[c * CHN + ch] = make_float4(A[0], A[1], A[2], A[3]);
    *(float4*)&g_S[c * CHN + ch] = make_float4(s[0], s[1], s[2], s[3]);
}

// ---------------------------------------------------------------------------
// Scan phase 2: 256 chunks per channel; one warp per channel, 8 chunks/lane.
// Compose rule (apply P then Q): (A,S) = (Aq*Ap, Aq*Sp + Sq); s0 = 0.
// ---------------------------------------------------------------------------
__global__ __launch_bounds__(256) void scan_phase2()
{
    const int lane = threadIdx.x & 31;
    const int ch   = blockIdx.x * 8 + (threadIdx.x >> 5);

    float A[8], S[8];
    #pragma unroll
    for (int j = 0; j < 8; j++) {
        A[j] = g_A[(8 * lane + j) * CHN + ch];
        S[j] = g_S[(8 * lane + j) * CHN + ch];
    }
    float Ac = A[0], Sc = S[0];
    #pragma unroll
    for (int j = 1; j < 8; j++) { Sc = fmaf(A[j], Sc, S[j]); Ac *= A[j]; }

    #pragma unroll
    for (int off = 1; off < 32; off <<= 1) {
        float Ap = __shfl_up_sync(0xffffffffu, Ac, off);
        float Sp = __shfl_up_sync(0xffffffffu, Sc, off);
        if (lane >= off) { Sc = fmaf(Ac, Sp, Sc); Ac *= Ap; }
    }
    float Pbase = __shfl_up_sync(0xffffffffu, Sc, 1);
    if (lane == 0) Pbase = 0.0f;

    float s = Pbase;
    #pragma unroll
    for (int j = 0; j < 8; j++) {
        g_P[(8 * lane + j) * CHN + ch] = s;
        s = fmaf(A[j], s, S[j]);
    }
}

// ---------------------------------------------------------------------------
// Scan phase 3: re-scan each chunk from its prefix; streaming fp32 stores.
// ---------------------------------------------------------------------------
__global__ __launch_bounds__(256) void scan_phase3(float* __restrict__ out)
{
    const int d = threadIdx.x * 4;
    const int b = blockIdx.x;
    const int c = blockIdx.y;
    const int ch = b * Dd + d;
    size_t base = ((size_t)(b * Kk + c * LCH)) * Dd + d;

    float4 p = *(const float4*)&g_P[c * CHN + ch];
    float s[4] = {p.x, p.y, p.z, p.w};
    #pragma unroll 8
    for (int k = 0; k < LCH; k++) {
        size_t idx = base + (size_t)k * Dd;
        uint2 lu = *(const uint2*)&g_lamh[idx];
        uint2 xu = *(const uint2*)&g_Xh[idx];
        float2 l0 = __half22float2(*(__half2*)&lu.x);
        float2 l1 = __half22float2(*(__half2*)&lu.y);
        float2 x0 = __half22float2(*(__half2*)&xu.x);
        float2 x1 = __half22float2(*(__half2*)&xu.y);
        s[0] = fmaf(l0.x, s[0] - x0.x, x0.x);
        s[1] = fmaf(l0.y, s[1] - x0.y, x0.y);
        s[2] = fmaf(l1.x, s[2] - x1.x, x1.x);
        s[3] = fmaf(l1.y, s[3] - x1.y, x1.y);
        __stcs((float4*)&out[idx], make_float4(s[0], s[1], s[2], s[3]));
    }
}

// ---------------------------------------------------------------------------
extern "C" void kernel_launch(void* const* d_in, const int* in_sizes, int n_in,
                              void* d_out, int out_size)
{
    const float* X    = (const float*)d_in[0];  // [B,K,D]
    const float* W    = (const float*)d_in[1];  // [D,D]
    const float* bias = (const float*)d_in[2];  // [D]
    float* out        = (float*)d_out;          // [B,K,D]

    __half* Xh; cudaGetSymbolAddress((void**)&Xh, g_Xh);
    __half* Wh; cudaGetSymbolAddress((void**)&Wh, g_Wh);
    f2h_kernel<<<1024, 256>>>((const float4*)X, (uint2*)Xh, (Mm * Dd) / 4);
    f2h_kernel<<<256, 256>>>((const float4*)W, (uint2*)Wh, (Dd * Dd) / 4);

    const int smem_bytes = SMEM_HALVES * (int)sizeof(__half);   // 120 KB
    cudaFuncSetAttribute(gemm_sigmoid_f16,
                         cudaFuncAttributeMaxDynamicSharedMemorySize, smem_bytes);

    dim3 gemm_grid(Dd / BN, Mm / BM);           // (4, 256)
    gemm_sigmoid_f16<<<gemm_grid, 256, smem_bytes>>>(bias);

    dim3 scan_grid(Bb, NCH);                    // (4, 256) = 1024 blocks
    scan_phase1<<<scan_grid, 256>>>();
    scan_phase2<<<CHN / 8, 256>>>();
    scan_phase3<<<scan_grid, 256>>>(out);
}